// round 5
// baseline (speedup 1.0000x reference)
#include <cuda_runtime.h>
#include <math.h>

// Problem capacities (padded a bit above the dataset sizes)
#define MAXN 100352
#define MAXE 3276800

// ---------------- scratch (__device__ globals; no allocation allowed) -------
__device__ int   g_deg[MAXN];
__device__ int   g_cursor[MAXN];
__device__ int   g_rowStart[MAXN];
__device__ int   g_part[1024];
__device__ float g_dinv[MAXN];
__device__ int   g_csr[MAXE];
__device__ int   g_is64;                     // 1 if edge_index is int64 on device
__device__ float g_buf1[(size_t)MAXN * 64];  // dinv-scaled  X@W1
__device__ float g_buf2[(size_t)MAXN * 64];  // h1 = relu(agg + b1)
__device__ float g_buf3[(size_t)MAXN * 64];  // dinv-scaled  h1@W2

// ---------------- dtype detection -------------------------------------------
__global__ void k_detect(const int* __restrict__ ei32, int nPairs) {
    __shared__ int sh[256];
    int t = threadIdx.x;
    int acc = 0;
    for (int i = t; i < nPairs; i += 256) acc |= ei32[2 * i + 1];
    sh[t] = acc; __syncthreads();
    for (int off = 128; off > 0; off >>= 1) {
        if (t < off) sh[t] |= sh[t + off];
        __syncthreads();
    }
    if (t == 0) g_is64 = (sh[0] == 0) ? 1 : 0;
}

__device__ __forceinline__ int load_idx(const void* ei, size_t pos) {
    if (g_is64) return (int)((const long long*)ei)[pos];
    return ((const int*)ei)[pos];
}

// ---------------- CSR build --------------------------------------------------
__global__ void k_zero(int N) {
    int i = blockIdx.x * blockDim.x + threadIdx.x;
    if (i < N) { g_deg[i] = 0; g_cursor[i] = 0; }
}

__global__ void k_hist(const void* __restrict__ ei, int E) {
    int e = blockIdx.x * blockDim.x + threadIdx.x;
    if (e < E) {
        int d = load_idx(ei, (size_t)E + e);
        atomicAdd(&g_deg[d], 1);
    }
}

__global__ void k_part(int N) {
    __shared__ int sh[256];
    int b = blockIdx.x, t = threadIdx.x, i = b * 256 + t;
    int v = (i < N) ? g_deg[i] : 0;
    sh[t] = v; __syncthreads();
    for (int off = 128; off > 0; off >>= 1) {
        if (t < off) sh[t] += sh[t + off];
        __syncthreads();
    }
    if (t == 0) g_part[b] = sh[0];
}

__global__ void k_top(int nb) {
    __shared__ int sh[1024];
    int t = threadIdx.x;
    int v = (t < nb) ? g_part[t] : 0;
    sh[t] = v; __syncthreads();
    for (int off = 1; off < 1024; off <<= 1) {
        int x = (t >= off) ? sh[t - off] : 0;
        __syncthreads();
        sh[t] += x;
        __syncthreads();
    }
    g_part[t] = sh[t] - v;   // exclusive
}

__global__ void k_scan(int N) {
    __shared__ int sh[256];
    int b = blockIdx.x, t = threadIdx.x, i = b * 256 + t;
    int v = (i < N) ? g_deg[i] : 0;
    sh[t] = v; __syncthreads();
    for (int off = 1; off < 256; off <<= 1) {
        int x = (t >= off) ? sh[t - off] : 0;
        __syncthreads();
        sh[t] += x;
        __syncthreads();
    }
    if (i < N) {
        g_rowStart[i] = g_part[b] + sh[t] - v;
        g_dinv[i] = rsqrtf((float)(v + 1));   // +1 self loop
    }
}

__global__ void k_scatter(const void* __restrict__ ei, int E) {
    int e = blockIdx.x * blockDim.x + threadIdx.x;
    if (e < E) {
        int s = load_idx(ei, (size_t)e);
        int d = load_idx(ei, (size_t)E + e);
        int pos = g_rowStart[d] + atomicAdd(&g_cursor[d], 1);
        g_csr[pos] = s;
    }
}

// ---------------- GEMM: C[m, 0:64] = dinv[m] * (A[m,:] @ B) ------------------
// BM=128, BN=64, BK=32, 256 threads, 8x4 micro-tile, k-step-2 inner loop.
__global__ void k_gemm(const float* __restrict__ Aext, const float* __restrict__ B,
                       int M, int K, int inSel, int outSel) {
    __shared__ float As[128][36];
    __shared__ float Bs[32][68];

    const float* A = (inSel == 0) ? Aext : (const float*)g_buf2;
    float* C = (outSel == 0) ? g_buf1 : g_buf3;

    int tid = threadIdx.x;
    int tx = tid & 15;
    int ty = tid >> 4;
    int m0 = blockIdx.x * 128;

    float acc[8][4];
#pragma unroll
    for (int i = 0; i < 8; i++)
#pragma unroll
        for (int j = 0; j < 4; j++) acc[i][j] = 0.0f;

    int nK = K >> 5;
    for (int kt = 0; kt < nK; kt++) {
        int k0 = kt * 32;
#pragma unroll
        for (int i = 0; i < 4; i++) {
            int idx = tid + i * 256;
            int row = idx >> 3, c4 = idx & 7;
            float4 v = make_float4(0.f, 0.f, 0.f, 0.f);
            int gr = m0 + row;
            if (gr < M) v = *(const float4*)(A + (size_t)gr * K + k0 + c4 * 4);
            *(float4*)&As[row][c4 * 4] = v;
        }
#pragma unroll
        for (int i = 0; i < 2; i++) {
            int idx = tid + i * 256;
            int row = idx >> 4, c4 = idx & 15;
            float4 v = *(const float4*)(B + (size_t)(k0 + row) * 64 + c4 * 4);
            *(float4*)&Bs[row][c4 * 4] = v;
        }
        __syncthreads();

#pragma unroll
        for (int k = 0; k < 32; k += 2) {
            float2 a[8];
#pragma unroll
            for (int i = 0; i < 8; i++) a[i] = *(float2*)&As[ty * 8 + i][k];
            float4 b0 = *(float4*)&Bs[k][tx * 4];
            float4 b1 = *(float4*)&Bs[k + 1][tx * 4];
#pragma unroll
            for (int i = 0; i < 8; i++) {
                acc[i][0] += a[i].x * b0.x; acc[i][1] += a[i].x * b0.y;
                acc[i][2] += a[i].x * b0.z; acc[i][3] += a[i].x * b0.w;
                acc[i][0] += a[i].y * b1.x; acc[i][1] += a[i].y * b1.y;
                acc[i][2] += a[i].y * b1.z; acc[i][3] += a[i].y * b1.w;
            }
        }
        __syncthreads();
    }

#pragma unroll
    for (int i = 0; i < 8; i++) {
        int gr = m0 + ty * 8 + i;
        if (gr < M) {
            float d = g_dinv[gr];
            float4 o = make_float4(acc[i][0] * d, acc[i][1] * d,
                                   acc[i][2] * d, acc[i][3] * d);
            *(float4*)(C + (size_t)gr * 64 + tx * 4) = o;
        }
    }
}

// ---------------- aggregation: one warp per dst node, paired-edge float4 -----
// Half-warp h (lanes 16h..16h+15) handles edge j+h; lane covers 4 channels.
// One LDG.128 warp-instruction gathers 2 full 256B source rows.
__global__ void k_agg(const float* __restrict__ bias, float* __restrict__ outExt,
                      int N, int inSel, int do_relu) {
    const float* hs = (inSel == 0) ? (const float*)g_buf1 : (const float*)g_buf3;
    float* out = (outExt != nullptr) ? outExt : (float*)g_buf2;

    int gw = (blockIdx.x * blockDim.x + threadIdx.x) >> 5;
    int lane = threadIdx.x & 31;
    if (gw >= N) return;

    int beg = g_rowStart[gw];
    int dg  = g_deg[gw];
    int half = lane >> 4;
    int c4   = (lane & 15) * 4;

    float4 acc = make_float4(0.f, 0.f, 0.f, 0.f);
    if (half == 0)   // self-loop contribution (already dinv-scaled)
        acc = *(const float4*)(hs + (size_t)gw * 64 + c4);

    int e = beg, end = beg + dg;
    while (e < end) {
        int rem = end - e;
        int idx = 0;
        if (lane < rem) idx = g_csr[e + lane];
        int cnt = rem < 32 ? rem : 32;
        int j = 0;
        for (; j + 8 <= cnt; j += 8) {
            int s0 = __shfl_sync(0xffffffffu, idx, j + half);
            int s1 = __shfl_sync(0xffffffffu, idx, j + 2 + half);
            int s2 = __shfl_sync(0xffffffffu, idx, j + 4 + half);
            int s3 = __shfl_sync(0xffffffffu, idx, j + 6 + half);
            float4 v0 = *(const float4*)(hs + (size_t)s0 * 64 + c4);
            float4 v1 = *(const float4*)(hs + (size_t)s1 * 64 + c4);
            float4 v2 = *(const float4*)(hs + (size_t)s2 * 64 + c4);
            float4 v3 = *(const float4*)(hs + (size_t)s3 * 64 + c4);
            acc.x += (v0.x + v1.x) + (v2.x + v3.x);
            acc.y += (v0.y + v1.y) + (v2.y + v3.y);
            acc.z += (v0.z + v1.z) + (v2.z + v3.z);
            acc.w += (v0.w + v1.w) + (v2.w + v3.w);
        }
        for (; j + 2 <= cnt; j += 2) {
            int s = __shfl_sync(0xffffffffu, idx, j + half);
            float4 v = *(const float4*)(hs + (size_t)s * 64 + c4);
            acc.x += v.x; acc.y += v.y; acc.z += v.z; acc.w += v.w;
        }
        if (j < cnt) {   // odd leftover edge: half 0 only
            int s = __shfl_sync(0xffffffffu, idx, j);
            if (half == 0) {
                float4 v = *(const float4*)(hs + (size_t)s * 64 + c4);
                acc.x += v.x; acc.y += v.y; acc.z += v.z; acc.w += v.w;
            }
        }
        e += 32;
    }

    // combine the two half-warp partial sums
    acc.x += __shfl_xor_sync(0xffffffffu, acc.x, 16);
    acc.y += __shfl_xor_sync(0xffffffffu, acc.y, 16);
    acc.z += __shfl_xor_sync(0xffffffffu, acc.z, 16);
    acc.w += __shfl_xor_sync(0xffffffffu, acc.w, 16);

    if (half == 0) {
        float di = g_dinv[gw];
        float4 b = *(const float4*)(bias + c4);
        float4 v = make_float4(di * acc.x + b.x, di * acc.y + b.y,
                               di * acc.z + b.z, di * acc.w + b.w);
        if (do_relu) {
            v.x = fmaxf(v.x, 0.f); v.y = fmaxf(v.y, 0.f);
            v.z = fmaxf(v.z, 0.f); v.w = fmaxf(v.w, 0.f);
        }
        *(float4*)(out + (size_t)gw * 64 + c4) = v;
    }
}

// ---------------- launch -----------------------------------------------------
extern "C" void kernel_launch(void* const* d_in, const int* in_sizes, int n_in,
                              void* d_out, int out_size) {
    const float* x  = (const float*)d_in[0];
    const void*  ei = d_in[1];                 // int32 or int64; detected on device
    const float* W1 = (const float*)d_in[2];
    const float* b1 = (const float*)d_in[3];
    const float* W2 = (const float*)d_in[4];
    const float* b2 = (const float*)d_in[5];
    float* out = (float*)d_out;

    int N = in_sizes[0] / 256;   // nodes
    int E = in_sizes[1] / 2;     // edges

    int nb = (N + 255) / 256;
    int eb = (E + 255) / 256;

    // ---- dtype detection + CSR build ----
    int nPairs = (E < 2048) ? E : 2048;
    k_detect<<<1, 256>>>((const int*)ei, nPairs);
    k_zero<<<nb, 256>>>(N);
    k_hist<<<eb, 256>>>(ei, E);
    k_part<<<nb, 256>>>(N);
    k_top<<<1, 1024>>>(nb);
    k_scan<<<nb, 256>>>(N);
    k_scatter<<<eb, 256>>>(ei, E);

    // ---- layer 1 ----
    int gemm_blocks = (N + 127) / 128;
    k_gemm<<<gemm_blocks, 256>>>(x, W1, N, 256, /*inSel=*/0, /*outSel=*/0);
    int agg_blocks = (N + 7) / 8;
    k_agg<<<agg_blocks, 256>>>(b1, nullptr, N, /*inSel=*/0, /*do_relu=*/1);

    // ---- layer 2 ----
    k_gemm<<<gemm_blocks, 256>>>(nullptr, W2, N, 64, /*inSel=*/1, /*outSel=*/1);
    k_agg<<<agg_blocks, 256>>>(b2, out, N, /*inSel=*/1, /*do_relu=*/0);
}

// round 6
// speedup vs baseline: 1.0579x; 1.0579x over previous
#include <cuda_runtime.h>
#include <cuda_fp16.h>
#include <math.h>

// Problem capacities (padded a bit above the dataset sizes)
#define MAXN 100352
#define MAXE 3276800

// ---------------- scratch (__device__ globals; no allocation allowed) -------
__device__ int     g_deg[MAXN];
__device__ int     g_cursor[MAXN];
__device__ int     g_rowStart[MAXN];
__device__ int     g_part[1024];
__device__ float   g_dinv[MAXN];
__device__ int     g_csr[MAXE];
__device__ int     g_is64;                       // 1 if edge_index is int64
__device__ __half2 g_hbuf1[(size_t)MAXN * 32];   // fp16: dinv-scaled X@W1
__device__ __half2 g_hbuf3[(size_t)MAXN * 32];   // fp16: dinv-scaled h1@W2
__device__ float   g_buf2[(size_t)MAXN * 64];    // fp32: h1 = relu(agg + b1)

// ---------------- dtype detection -------------------------------------------
__global__ void k_detect(const int* __restrict__ ei32, int nPairs) {
    __shared__ int sh[256];
    int t = threadIdx.x;
    int acc = 0;
    for (int i = t; i < nPairs; i += 256) acc |= ei32[2 * i + 1];
    sh[t] = acc; __syncthreads();
    for (int off = 128; off > 0; off >>= 1) {
        if (t < off) sh[t] |= sh[t + off];
        __syncthreads();
    }
    if (t == 0) g_is64 = (sh[0] == 0) ? 1 : 0;
}

__device__ __forceinline__ int load_idx(const void* ei, size_t pos) {
    if (g_is64) return (int)((const long long*)ei)[pos];
    return ((const int*)ei)[pos];
}

// ---------------- CSR build --------------------------------------------------
__global__ void k_zero(int N) {
    int i = blockIdx.x * blockDim.x + threadIdx.x;
    if (i < N) { g_deg[i] = 0; g_cursor[i] = 0; }
}

__global__ void k_hist(const void* __restrict__ ei, int E) {
    int e = blockIdx.x * blockDim.x + threadIdx.x;
    if (e < E) {
        int d = load_idx(ei, (size_t)E + e);
        atomicAdd(&g_deg[d], 1);
    }
}

__global__ void k_part(int N) {
    __shared__ int sh[256];
    int b = blockIdx.x, t = threadIdx.x, i = b * 256 + t;
    int v = (i < N) ? g_deg[i] : 0;
    sh[t] = v; __syncthreads();
    for (int off = 128; off > 0; off >>= 1) {
        if (t < off) sh[t] += sh[t + off];
        __syncthreads();
    }
    if (t == 0) g_part[b] = sh[0];
}

__global__ void k_top(int nb) {
    __shared__ int sh[1024];
    int t = threadIdx.x;
    int v = (t < nb) ? g_part[t] : 0;
    sh[t] = v; __syncthreads();
    for (int off = 1; off < 1024; off <<= 1) {
        int x = (t >= off) ? sh[t - off] : 0;
        __syncthreads();
        sh[t] += x;
        __syncthreads();
    }
    g_part[t] = sh[t] - v;   // exclusive
}

__global__ void k_scan(int N) {
    __shared__ int sh[256];
    int b = blockIdx.x, t = threadIdx.x, i = b * 256 + t;
    int v = (i < N) ? g_deg[i] : 0;
    sh[t] = v; __syncthreads();
    for (int off = 1; off < 256; off <<= 1) {
        int x = (t >= off) ? sh[t - off] : 0;
        __syncthreads();
        sh[t] += x;
        __syncthreads();
    }
    if (i < N) {
        g_rowStart[i] = g_part[b] + sh[t] - v;
        g_dinv[i] = rsqrtf((float)(v + 1));   // +1 self loop
    }
}

__global__ void k_scatter(const void* __restrict__ ei, int E) {
    int e = blockIdx.x * blockDim.x + threadIdx.x;
    if (e < E) {
        int s = load_idx(ei, (size_t)e);
        int d = load_idx(ei, (size_t)E + e);
        int pos = g_rowStart[d] + atomicAdd(&g_cursor[d], 1);
        g_csr[pos] = s;
    }
}

// ---------------- GEMM: Chalf[m, 0:64] = fp16( dinv[m] * (A[m,:] @ B) ) -----
// BM=128, BN=64, BK=32, 256 threads, 8x4 micro-tile (exact R4 inner loop).
__global__ void k_gemm(const float* __restrict__ Aext, const float* __restrict__ B,
                       int M, int K, int inSel, int outSel) {
    __shared__ float As[128][36];
    __shared__ float Bs[32][68];

    const float* A = (inSel == 0) ? Aext : (const float*)g_buf2;
    __half2* C = (outSel == 0) ? g_hbuf1 : g_hbuf3;

    int tid = threadIdx.x;
    int tx = tid & 15;
    int ty = tid >> 4;
    int m0 = blockIdx.x * 128;

    float acc[8][4];
#pragma unroll
    for (int i = 0; i < 8; i++)
#pragma unroll
        for (int j = 0; j < 4; j++) acc[i][j] = 0.0f;

    int nK = K >> 5;
    for (int kt = 0; kt < nK; kt++) {
        int k0 = kt * 32;
#pragma unroll
        for (int i = 0; i < 4; i++) {
            int idx = tid + i * 256;
            int row = idx >> 3, c4 = idx & 7;
            float4 v = make_float4(0.f, 0.f, 0.f, 0.f);
            int gr = m0 + row;
            if (gr < M) v = *(const float4*)(A + (size_t)gr * K + k0 + c4 * 4);
            *(float4*)&As[row][c4 * 4] = v;
        }
#pragma unroll
        for (int i = 0; i < 2; i++) {
            int idx = tid + i * 256;
            int row = idx >> 4, c4 = idx & 15;
            float4 v = *(const float4*)(B + (size_t)(k0 + row) * 64 + c4 * 4);
            *(float4*)&Bs[row][c4 * 4] = v;
        }
        __syncthreads();

#pragma unroll
        for (int k = 0; k < 32; k++) {
            float a[8];
#pragma unroll
            for (int i = 0; i < 8; i++) a[i] = As[ty * 8 + i][k];
            float4 bv = *(float4*)&Bs[k][tx * 4];
            float b[4] = {bv.x, bv.y, bv.z, bv.w};
#pragma unroll
            for (int i = 0; i < 8; i++)
#pragma unroll
                for (int j = 0; j < 4; j++) acc[i][j] += a[i] * b[j];
        }
        __syncthreads();
    }

#pragma unroll
    for (int i = 0; i < 8; i++) {
        int gr = m0 + ty * 8 + i;
        if (gr < M) {
            float d = g_dinv[gr];
            __half2 h0 = __floats2half2_rn(acc[i][0] * d, acc[i][1] * d);
            __half2 h1 = __floats2half2_rn(acc[i][2] * d, acc[i][3] * d);
            __half2* p = C + (size_t)gr * 32 + tx * 2;
            p[0] = h0;
            p[1] = h1;
        }
    }
}

// ---------------- aggregation: one warp per dst node, fp16 rows --------------
// hs rows (32 x half2) already scaled by dinv[src]. Lane covers channels
// {2*lane, 2*lane+1}. One LDG.64 warp-instruction per edge (128B row).
__global__ void k_agg(const float* __restrict__ bias, float* __restrict__ outExt,
                      int N, int inSel, int do_relu) {
    const __half2* hs = (inSel == 0) ? (const __half2*)g_hbuf1
                                     : (const __half2*)g_hbuf3;
    float* out = (outExt != nullptr) ? outExt : (float*)g_buf2;

    int gw = (blockIdx.x * blockDim.x + threadIdx.x) >> 5;
    int lane = threadIdx.x & 31;
    if (gw >= N) return;

    int beg = g_rowStart[gw];
    int dg  = g_deg[gw];

    float2 self = __half22float2(hs[(size_t)gw * 32 + lane]);
    float acc0 = self.x, acc1 = self.y;   // self-loop (already dinv-scaled)

    int e = beg, end = beg + dg;
    while (e < end) {
        int rem = end - e;
        int idx = 0;
        if (lane < rem) idx = g_csr[e + lane];
        int cnt = rem < 32 ? rem : 32;
        int j = 0;
        for (; j + 4 <= cnt; j += 4) {
            int s0 = __shfl_sync(0xffffffffu, idx, j);
            int s1 = __shfl_sync(0xffffffffu, idx, j + 1);
            int s2 = __shfl_sync(0xffffffffu, idx, j + 2);
            int s3 = __shfl_sync(0xffffffffu, idx, j + 3);
            float2 v0 = __half22float2(hs[(size_t)s0 * 32 + lane]);
            float2 v1 = __half22float2(hs[(size_t)s1 * 32 + lane]);
            float2 v2 = __half22float2(hs[(size_t)s2 * 32 + lane]);
            float2 v3 = __half22float2(hs[(size_t)s3 * 32 + lane]);
            acc0 += (v0.x + v1.x) + (v2.x + v3.x);
            acc1 += (v0.y + v1.y) + (v2.y + v3.y);
        }
        for (; j < cnt; j++) {
            int s = __shfl_sync(0xffffffffu, idx, j);
            float2 v = __half22float2(hs[(size_t)s * 32 + lane]);
            acc0 += v.x;
            acc1 += v.y;
        }
        e += 32;
    }

    float di = g_dinv[gw];
    float2 b = *(const float2*)(bias + 2 * lane);
    float v0 = di * acc0 + b.x;
    float v1 = di * acc1 + b.y;
    if (do_relu) { v0 = fmaxf(v0, 0.f); v1 = fmaxf(v1, 0.f); }
    *(float2*)(out + (size_t)gw * 64 + 2 * lane) = make_float2(v0, v1);
}

// ---------------- launch -----------------------------------------------------
extern "C" void kernel_launch(void* const* d_in, const int* in_sizes, int n_in,
                              void* d_out, int out_size) {
    const float* x  = (const float*)d_in[0];
    const void*  ei = d_in[1];                 // int32 or int64; detected on device
    const float* W1 = (const float*)d_in[2];
    const float* b1 = (const float*)d_in[3];
    const float* W2 = (const float*)d_in[4];
    const float* b2 = (const float*)d_in[5];
    float* out = (float*)d_out;

    int N = in_sizes[0] / 256;   // nodes
    int E = in_sizes[1] / 2;     // edges

    int nb = (N + 255) / 256;
    int eb = (E + 255) / 256;

    // ---- dtype detection + CSR build ----
    int nPairs = (E < 2048) ? E : 2048;
    k_detect<<<1, 256>>>((const int*)ei, nPairs);
    k_zero<<<nb, 256>>>(N);
    k_hist<<<eb, 256>>>(ei, E);
    k_part<<<nb, 256>>>(N);
    k_top<<<1, 1024>>>(nb);
    k_scan<<<nb, 256>>>(N);
    k_scatter<<<eb, 256>>>(ei, E);

    // ---- layer 1 ----
    int gemm_blocks = (N + 127) / 128;
    k_gemm<<<gemm_blocks, 256>>>(x, W1, N, 256, /*inSel=*/0, /*outSel=*/0);
    int agg_blocks = (N + 7) / 8;
    k_agg<<<agg_blocks, 256>>>(b1, nullptr, N, /*inSel=*/0, /*do_relu=*/1);

    // ---- layer 2 ----
    k_gemm<<<gemm_blocks, 256>>>(nullptr, W2, N, 64, /*inSel=*/1, /*outSel=*/1);
    k_agg<<<agg_blocks, 256>>>(b2, out, N, /*inSel=*/1, /*do_relu=*/0);
}